// round 15
// baseline (speedup 1.0000x reference)
#include <cuda_runtime.h>
#include <math.h>
#include <stdint.h>

#define BSZ   128
#define TLEN  256
#define NCLS  128
#define WDIM  512
#define UNITS 512
#define JDIM  2048   // 4*UNITS
#define KX    640    // NC+WD (x-part of IN_DIM)

// ---------------- persistent device scratch ------------------------------------------
__device__ float g_Xproj[(size_t)TLEN * BSZ * JDIM];  // [t][b][j] = bias + x@Wx
__device__ float g_h[2][BSZ * UNITS];   // ping-pong h buffers, layout [b][unit]
__device__ float g_c[BSZ * UNITS];      // cell state (owner-block private)
__device__ float g_wsum[JDIM];          // 1e-5 * colsum of word rows of W
__device__ float g_part[BSZ * 16 * NCLS]; // partial logits [b][ut][m]

// ---------------- accurate fp32 math independent of -use_fast_math ----------------
__device__ __forceinline__ float my_exp(float x) {
    float t = x * 1.4426950408889634f;
    float n = rintf(t);
    float f = t - n;
    float p =             1.5252733e-5f;
    p = fmaf(p, f, 1.5403530e-4f);
    p = fmaf(p, f, 1.3333558e-3f);
    p = fmaf(p, f, 9.6181291e-3f);
    p = fmaf(p, f, 5.5504109e-2f);
    p = fmaf(p, f, 2.4022647e-1f);
    p = fmaf(p, f, 6.9314718e-1f);
    p = fmaf(p, f, 1.0f);
    return ldexpf(p, (int)n);
}
__device__ __forceinline__ float my_sigmoid(float x) {
    return 1.0f / (1.0f + my_exp(-x));
}
__device__ __forceinline__ float my_tanh(float x) {
    if (x >  20.0f) return  1.0f;
    if (x < -20.0f) return -1.0f;
    float e = my_exp(2.0f * x);
    return (e - 1.0f) / (e + 1.0f);
}

// ---------------- cp.async helpers ----------------------------------------------------
__device__ __forceinline__ uint32_t smem_u32(const void* p) {
    uint32_t a;
    asm("{ .reg .u64 t; cvta.to.shared.u64 t, %1; cvt.u32.u64 %0, t; }"
        : "=r"(a) : "l"(p));
    return a;
}
__device__ __forceinline__ void cp_async16(uint32_t dst, const void* src) {
    asm volatile("cp.async.cg.shared.global [%0], [%1], 16;" :: "r"(dst), "l"(src));
}
__device__ __forceinline__ void cp_commit() {
    asm volatile("cp.async.commit_group;");
}
__device__ __forceinline__ void cp_wait2() {
    asm volatile("cp.async.wait_group 2;");
}
__device__ __forceinline__ void cp_wait1() {
    asm volatile("cp.async.wait_group 1;");
}
__device__ __forceinline__ void cp_wait0() {
    asm volatile("cp.async.wait_group 0;");
}

// ---------------- init ----------------------------------------------------------------
__global__ void init_kernel() {
    int i = blockIdx.x * blockDim.x + threadIdx.x;
    if (i < BSZ * UNITS) {
        g_h[0][i] = 0.0f;
        g_h[1][i] = 0.0f;
        g_c[i]    = 0.0f;
    }
}

// ---------------- word-row column sums -------------------------------------------------
__global__ void wsum_kernel(const float* __restrict__ W) {
    int j = blockIdx.x * blockDim.x + threadIdx.x;
    if (j < JDIM) {
        float s = 0.0f;
        for (int r = 0; r < NCLS; ++r) s += W[(size_t)(KX + r) * JDIM + j];
        g_wsum[j] = 1e-5f * s;
    }
}

// ---------------- Xproj[t][b][j] = bias[j] + sum_{k<640} x[t,b,k] * W[k][j] ----------
// (verbatim from passing rounds)
__global__ __launch_bounds__(256) void xproj_kernel(
    const float* __restrict__ xc, const float* __restrict__ xw,
    const float* __restrict__ W, const float* __restrict__ bias)
{
    __shared__ float As[16][128];
    __shared__ float Bs[16][128];
    const int t   = blockIdx.y;
    const int n0  = blockIdx.x * 128;
    const int tid = threadIdx.x;
    const int tr  = tid >> 4;
    const int tc  = tid & 15;

    float acc[8][8];
#pragma unroll
    for (int i = 0; i < 8; ++i)
#pragma unroll
        for (int j = 0; j < 8; ++j) acc[i][j] = 0.0f;

    for (int k0 = 0; k0 < KX; k0 += 16) {
        for (int i = tid; i < 512; i += 256) {
            int bb = i >> 2;
            int kq = i & 3;
            int k  = k0 + kq * 4;
            const float* src = (k < NCLS)
                ? (xc + ((size_t)bb * TLEN + t) * NCLS + k)
                : (xw + ((size_t)bb * TLEN + t) * WDIM + (k - NCLS));
            float4 v = *(const float4*)src;
            As[kq*4+0][bb] = v.x;
            As[kq*4+1][bb] = v.y;
            As[kq*4+2][bb] = v.z;
            As[kq*4+3][bb] = v.w;
        }
        for (int i = tid; i < 512; i += 256) {
            int kk = i >> 5;
            int nq = i & 31;
            *(float4*)&Bs[kk][nq*4] =
                *(const float4*)(W + (size_t)(k0+kk)*JDIM + n0 + nq*4);
        }
        __syncthreads();
#pragma unroll
        for (int k = 0; k < 16; ++k) {
            float a[8], b8[8];
#pragma unroll
            for (int i = 0; i < 8; ++i) a[i] = As[k][tr*8 + i];
#pragma unroll
            for (int q = 0; q < 4; ++q) { b8[q] = Bs[k][tc*4 + q]; b8[4+q] = Bs[k][tc*4 + 64 + q]; }
#pragma unroll
            for (int i = 0; i < 8; ++i)
#pragma unroll
                for (int j = 0; j < 8; ++j) acc[i][j] = fmaf(a[i], b8[j], acc[i][j]);
        }
        __syncthreads();
    }
    float bv[8];
#pragma unroll
    for (int q = 0; q < 4; ++q) { bv[q] = bias[n0 + tc*4 + q]; bv[4+q] = bias[n0 + tc*4 + 64 + q]; }
#pragma unroll
    for (int i = 0; i < 8; ++i) {
        int b = tr*8 + i;
        size_t row = ((size_t)t * BSZ + b) * JDIM + n0;
        float4 v0 = make_float4(acc[i][0]+bv[0], acc[i][1]+bv[1], acc[i][2]+bv[2], acc[i][3]+bv[3]);
        float4 v1 = make_float4(acc[i][4]+bv[4], acc[i][5]+bv[5], acc[i][6]+bv[6], acc[i][7]+bv[7]);
        *(float4*)(g_Xproj + row + tc*4)      = v0;
        *(float4*)(g_Xproj + row + tc*4 + 64) = v1;
    }
}

// ---------------- smem layout for step kernel (floats) -------------------------------
#define SOF_B    0          // [4][64][128] U chunks (quad buffer)     32768
#define SOF_A    32768      // [16][512]    full h tile                 8192
#define SOF_Z    40960      // [16][128]    z tile                      2048
#define SOF_WSL  43008      // [32][128]    Ws slice                    4096
#define SOF_HN   47104      // [16][32]     h_new tile                   512
#define SOF_IDX  47616      // [16] ints    per-batch argmax              16
#define STEP_SMEM_FLOATS 47632
#define STEP_SMEM_BYTES  (STEP_SMEM_FLOATS * 4)

// ---------------- one LSTM time step: argmax(t-1) prologue + h@U + partial logits ----
// 128 blocks = 8 b-tiles x 16 u-tiles; 512 threads (16 warps/SM for latency hiding).
// h tile (16x512) loaded ONCE per step; U quad-buffered with prefetch distance 2
// => one __syncthreads per k-chunk. Thread = 2 batches x 2 j-cols (scalar fmaf,
// identical k-order to all passing rounds).
__global__ __launch_bounds__(512) void step_kernel(
    int t, const float* __restrict__ W, const float* __restrict__ Umat,
    const float* __restrict__ Ws, const float* __restrict__ bsv,
    float* __restrict__ out)
{
    extern __shared__ float sm[];
    float* B_s  = sm + SOF_B;
    float* A_s  = sm + SOF_A;
    float* zbuf = sm + SOF_Z;
    float* Wsl  = sm + SOF_WSL;
    float* hn   = sm + SOF_HN;
    int*   idx_s = (int*)(sm + SOF_IDX);

    const int tid = threadIdx.x;
    const int blk = blockIdx.x;
    const int b0  = (blk >> 4) * 16;
    const int ut  = blk & 15;
    const int u0  = ut * 32;
    const float* hin  = g_h[t & 1];
    float*       hout = g_h[(t + 1) & 1];
    const uint32_t sb = smem_u32(sm);

    // ---- group 0: Ws slice + FULL h tile + U chunk 0 ----
    for (int it = 0; it < 2; ++it) {                 // Wsl: 1024 float4
        int idx = tid + it * 512;
        int uu  = idx >> 5;
        int mq  = (idx & 31) * 4;
        cp_async16(sb + (uint32_t)((SOF_WSL + uu * 128 + mq) * 4),
                   Ws + (size_t)(u0 + uu) * NCLS + mq);
    }
    for (int it = 0; it < 4; ++it) {                 // A: 2048 float4 (16 x 512)
        int idx = tid + it * 512;
        int bl  = idx >> 7;
        int kq  = (idx & 127) * 4;
        cp_async16(sb + (uint32_t)((SOF_A + bl * 512 + kq) * 4),
                   hin + (size_t)(b0 + bl) * UNITS + kq);
    }
    for (int it = 0; it < 4; ++it) {                 // B0: 2048 float4
        int idx = tid + it * 512;
        int kk  = idx >> 5;
        int c   = (idx & 31) * 4;
        int g   = c >> 5;
        int uu  = c & 31;
        cp_async16(sb + (uint32_t)((SOF_B + kk * 128 + c) * 4),
                   Umat + (size_t)kk * JDIM + g * 512 + u0 + uu);
    }
    cp_commit();
    // ---- group 1: U chunk 1 ----
    for (int it = 0; it < 4; ++it) {
        int idx = tid + it * 512;
        int kk  = idx >> 5;
        int c   = (idx & 31) * 4;
        int g   = c >> 5;
        int uu  = c & 31;
        cp_async16(sb + (uint32_t)((SOF_B + 8192 + kk * 128 + c) * 4),
                   Umat + (size_t)(64 + kk) * JDIM + g * 512 + u0 + uu);
    }
    cp_commit();

    // ---- prologue: argmax of step t-1 logits; warp w handles batch b0+w ----
    // Identical summation order (ascending ut, then +bias) and first-index
    // tie-breaking as all passing rounds.
    const int lane = tid & 31;
    const int w    = tid >> 5;
    if (t > 0) {
        int m4 = lane * 4;
        float4 bs4 = *(const float4*)(bsv + m4);
        int b = b0 + w;
        const float* pbp = g_part + (size_t)b * (16 * NCLS) + m4;
        float4 s = make_float4(0.0f, 0.0f, 0.0f, 0.0f);
#pragma unroll
        for (int utl = 0; utl < 16; ++utl) {
            float4 v = *(const float4*)(pbp + utl * NCLS);
            s.x += v.x; s.y += v.y; s.z += v.z; s.w += v.w;
        }
        s.x += bs4.x; s.y += bs4.y; s.z += bs4.z; s.w += bs4.w;
        float bv = s.x; int bi = m4;
        if (s.y > bv) { bv = s.y; bi = m4 + 1; }
        if (s.z > bv) { bv = s.z; bi = m4 + 2; }
        if (s.w > bv) { bv = s.w; bi = m4 + 3; }
#pragma unroll
        for (int off = 16; off > 0; off >>= 1) {
            float ov = __shfl_down_sync(0xffffffffu, bv, off);
            int   oi = __shfl_down_sync(0xffffffffu, bi, off);
            if (ov > bv || (ov == bv && oi < bi)) { bv = ov; bi = oi; }
        }
        if (lane == 0) {
            idx_s[w] = bi;
            if (ut == 0) out[(size_t)b * TLEN + (t - 1)] = (float)bi;
        }
    }

    // ---- GEMM: thread = 2 batches (bp, bp+1) x 2 j-cols (jp, jp+1), scalar fmaf ----
    const int bp = (tid >> 6) * 2;    // 0,2,..,14  (warp-uniform pair)
    const int jp = (tid & 63) * 2;    // 0..126

    float a00 = 0.0f, a01 = 0.0f, a10 = 0.0f, a11 = 0.0f;
    const float* Ar0 = A_s + bp * 512;
    const float* Ar1 = A_s + (bp + 1) * 512;

#pragma unroll
    for (int kc = 0; kc < 8; ++kc) {
        if (kc < 6) {   // prefetch chunk kc+2 into buf (kc+2)%4
            int nc  = kc + 2;
            int buf = nc & 3;
            for (int it = 0; it < 4; ++it) {
                int idx = tid + it * 512;
                int kk  = idx >> 5;
                int c   = (idx & 31) * 4;
                int g   = c >> 5;
                int uu  = c & 31;
                cp_async16(sb + (uint32_t)((SOF_B + buf * 8192 + kk * 128 + c) * 4),
                           Umat + (size_t)(nc * 64 + kk) * JDIM + g * 512 + u0 + uu);
            }
            cp_commit();
            cp_wait2();
        } else if (kc == 6) {
            cp_wait1();
        } else {
            cp_wait0();
        }
        __syncthreads();
        const float* Bb = B_s + (kc & 3) * 8192;
        const float* a0p = Ar0 + kc * 64;
        const float* a1p = Ar1 + kc * 64;
#pragma unroll 16
        for (int kk = 0; kk < 64; ++kk) {
            float2 u2 = *(const float2*)&Bb[kk * 128 + jp];
            float h0 = a0p[kk];
            float h1 = a1p[kk];
            a00 = fmaf(h0, u2.x, a00);
            a01 = fmaf(h0, u2.y, a01);
            a10 = fmaf(h1, u2.x, a10);
            a11 = fmaf(h1, u2.y, a11);
        }
    }
    __syncthreads();   // all compute done before zbuf write (zbuf aliases nothing, but order prologue idx writes too)
    *(float2*)&zbuf[bp * 128 + jp]       = make_float2(a00, a01);
    *(float2*)&zbuf[(bp + 1) * 128 + jp] = make_float2(a10, a11);
    __syncthreads();

    // ---- finalize: gates + cell update; 1 (b,uu) pair per thread ----
    const float* xbase = g_Xproj + (size_t)t * BSZ * JDIM;
    {
        int bl = tid >> 5;
        int uu = tid & 31;
        int b  = b0 + bl;
        int widx = (t == 0) ? -1 : idx_s[bl];
        float z[4];
#pragma unroll
        for (int g = 0; g < 4; ++g) {
            int j = g * 512 + u0 + uu;
            float wrow = (widx < 0) ? g_wsum[j]
                                    : W[(size_t)(KX + widx) * JDIM + j];
            z[g] = zbuf[bl * 128 + g * 32 + uu] + xbase[(size_t)b * JDIM + j] + wrow;
        }
        float ig = my_sigmoid(z[0]);
        float fg = my_sigmoid(z[1]);
        float gg = my_tanh(z[2]);
        float og = my_sigmoid(z[3]);
        size_t ci = (size_t)b * UNITS + u0 + uu;
        float cn = fmaf(fg, g_c[ci], ig * gg);
        g_c[ci] = cn;
        float hv = og * my_tanh(cn);
        hout[ci] = hv;
        hn[bl * 32 + uu] = hv;
    }
    __syncthreads();

    // ---- partial logits for this u-slice: g_part[b][ut][m] ----
    {
        int m  = tid & 127;
        int bh = tid >> 7;            // 0..3 -> batches bh*4 .. bh*4+3
        float pacc[4];
#pragma unroll
        for (int r = 0; r < 4; ++r) pacc[r] = 0.0f;
#pragma unroll 8
        for (int uu = 0; uu < 32; ++uu) {
            float wv = Wsl[uu * 128 + m];
#pragma unroll
            for (int r = 0; r < 4; ++r)
                pacc[r] = fmaf(hn[(bh * 4 + r) * 32 + uu], wv, pacc[r]);
        }
#pragma unroll
        for (int r = 0; r < 4; ++r) {
            int b = b0 + bh * 4 + r;
            g_part[(size_t)b * (16 * NCLS) + ut * NCLS + m] = pacc[r];
        }
    }
}

// ---------------- trailing argmax for t = 255 ----------------------------------------
__global__ __launch_bounds__(128) void argmax_last_kernel(
    const float* __restrict__ bsv, float* __restrict__ out)
{
    __shared__ float lg[NCLS];
    const int b   = blockIdx.x;
    const int tid = threadIdx.x;    // = class m

    float s = 0.0f;
    const float* pb = g_part + (size_t)b * (16 * NCLS);
#pragma unroll
    for (int utl = 0; utl < 16; ++utl)
        s += pb[utl * NCLS + tid];
    lg[tid] = s + bsv[tid];
    __syncthreads();

    if (tid < 32) {
        float bv = -INFINITY; int bi = 0x7fffffff;
        for (int mm = tid; mm < 128; mm += 32) {
            float v = lg[mm];
            if (v > bv) { bv = v; bi = mm; }
        }
#pragma unroll
        for (int off = 16; off > 0; off >>= 1) {
            float ov = __shfl_down_sync(0xffffffffu, bv, off);
            int   oi = __shfl_down_sync(0xffffffffu, bi, off);
            if (ov > bv || (ov == bv && oi < bi)) { bv = ov; bi = oi; }
        }
        if (tid == 0)
            out[(size_t)b * TLEN + (TLEN - 1)] = (float)bi;
    }
}

// ---------------- harness entry ------------------------------------------------------
extern "C" void kernel_launch(void* const* d_in, const int* in_sizes, int n_in,
                              void* d_out, int out_size) {
    (void)out_size;
    const float *xc = 0, *xw = 0, *W = 0, *U = 0, *bb = 0, *Ws = 0, *bs = 0;
    for (int i = 0; i < n_in; ++i) {
        switch (in_sizes[i]) {
            case BSZ*TLEN*NCLS:   xc = (const float*)d_in[i]; break;
            case BSZ*TLEN*WDIM:   xw = (const float*)d_in[i]; break;
            case (KX+NCLS)*JDIM:  W  = (const float*)d_in[i]; break;
            case UNITS*JDIM:      U  = (const float*)d_in[i]; break;
            case JDIM:            bb = (const float*)d_in[i]; break;
            case UNITS*NCLS:      Ws = (const float*)d_in[i]; break;
            case NCLS:            bs = (const float*)d_in[i]; break;
            default: break;
        }
    }
    if (!xc || !xw || !W || !U || !bb || !Ws || !bs) {
        xc = (const float*)d_in[0]; xw = (const float*)d_in[1];
        W  = (const float*)d_in[2]; U  = (const float*)d_in[3];
        bb = (const float*)d_in[4]; Ws = (const float*)d_in[5];
        bs = (const float*)d_in[6];
    }
    float* out = (float*)d_out;                // [128,256] as float32

    cudaFuncSetAttribute(step_kernel,
                         cudaFuncAttributeMaxDynamicSharedMemorySize, STEP_SMEM_BYTES);

    init_kernel<<<(BSZ*UNITS + 255) / 256, 256>>>();
    wsum_kernel<<<(JDIM + 255) / 256, 256>>>(W);
    dim3 gx(JDIM / 128, TLEN);
    xproj_kernel<<<gx, 256>>>(xc, xw, W, bb);
    for (int t = 0; t < TLEN; ++t) {
        step_kernel<<<128, 512, STEP_SMEM_BYTES>>>(t, W, U, Ws, bs, out);
    }
    argmax_last_kernel<<<128, 128>>>(bs, out);
}

// round 17
// speedup vs baseline: 1.0753x; 1.0753x over previous
#include <cuda_runtime.h>
#include <math.h>
#include <stdint.h>

#define BSZ   128
#define TLEN  256
#define NCLS  128
#define WDIM  512
#define UNITS 512
#define JDIM  2048   // 4*UNITS
#define KX    640    // NC+WD (x-part of IN_DIM)

// ---------------- persistent device scratch ------------------------------------------
__device__ float g_Xproj[(size_t)TLEN * BSZ * JDIM];  // [t][b][j] = bias + x@Wx
__device__ float g_h[2][BSZ * UNITS];   // ping-pong h buffers, layout [b][unit]
__device__ float g_c[BSZ * UNITS];      // cell state (owner-block private)
__device__ float g_wsum[JDIM];          // 1e-5 * colsum of word rows of W
__device__ float g_part[BSZ * 16 * NCLS]; // partial logits [b][ut][m]

// ---------------- accurate fp32 math independent of -use_fast_math ----------------
__device__ __forceinline__ float my_exp(float x) {
    float t = x * 1.4426950408889634f;
    float n = rintf(t);
    float f = t - n;
    float p =             1.5252733e-5f;
    p = fmaf(p, f, 1.5403530e-4f);
    p = fmaf(p, f, 1.3333558e-3f);
    p = fmaf(p, f, 9.6181291e-3f);
    p = fmaf(p, f, 5.5504109e-2f);
    p = fmaf(p, f, 2.4022647e-1f);
    p = fmaf(p, f, 6.9314718e-1f);
    p = fmaf(p, f, 1.0f);
    return ldexpf(p, (int)n);
}
__device__ __forceinline__ float my_sigmoid(float x) {
    return 1.0f / (1.0f + my_exp(-x));
}
__device__ __forceinline__ float my_tanh(float x) {
    if (x >  20.0f) return  1.0f;
    if (x < -20.0f) return -1.0f;
    float e = my_exp(2.0f * x);
    return (e - 1.0f) / (e + 1.0f);
}

// ---------------- cp.async helpers ----------------------------------------------------
__device__ __forceinline__ uint32_t smem_u32(const void* p) {
    uint32_t a;
    asm("{ .reg .u64 t; cvta.to.shared.u64 t, %1; cvt.u32.u64 %0, t; }"
        : "=r"(a) : "l"(p));
    return a;
}
__device__ __forceinline__ void cp_async16(uint32_t dst, const void* src) {
    asm volatile("cp.async.cg.shared.global [%0], [%1], 16;" :: "r"(dst), "l"(src));
}
__device__ __forceinline__ void cp_commit() {
    asm volatile("cp.async.commit_group;");
}
__device__ __forceinline__ void cp_wait2() {
    asm volatile("cp.async.wait_group 2;");
}
__device__ __forceinline__ void cp_wait1() {
    asm volatile("cp.async.wait_group 1;");
}
__device__ __forceinline__ void cp_wait0() {
    asm volatile("cp.async.wait_group 0;");
}

// ---------------- init ----------------------------------------------------------------
__global__ void init_kernel() {
    int i = blockIdx.x * blockDim.x + threadIdx.x;
    if (i < BSZ * UNITS) {
        g_h[0][i] = 0.0f;
        g_h[1][i] = 0.0f;
        g_c[i]    = 0.0f;
    }
}

// ---------------- word-row column sums -------------------------------------------------
__global__ void wsum_kernel(const float* __restrict__ W) {
    int j = blockIdx.x * blockDim.x + threadIdx.x;
    if (j < JDIM) {
        float s = 0.0f;
        for (int r = 0; r < NCLS; ++r) s += W[(size_t)(KX + r) * JDIM + j];
        g_wsum[j] = 1e-5f * s;
    }
}

// ---------------- Xproj[t][b][j] = bias[j] + sum_{k<640} x[t,b,k] * W[k][j] ----------
// (verbatim from passing rounds)
__global__ __launch_bounds__(256) void xproj_kernel(
    const float* __restrict__ xc, const float* __restrict__ xw,
    const float* __restrict__ W, const float* __restrict__ bias)
{
    __shared__ float As[16][128];
    __shared__ float Bs[16][128];
    const int t   = blockIdx.y;
    const int n0  = blockIdx.x * 128;
    const int tid = threadIdx.x;
    const int tr  = tid >> 4;
    const int tc  = tid & 15;

    float acc[8][8];
#pragma unroll
    for (int i = 0; i < 8; ++i)
#pragma unroll
        for (int j = 0; j < 8; ++j) acc[i][j] = 0.0f;

    for (int k0 = 0; k0 < KX; k0 += 16) {
        for (int i = tid; i < 512; i += 256) {
            int bb = i >> 2;
            int kq = i & 3;
            int k  = k0 + kq * 4;
            const float* src = (k < NCLS)
                ? (xc + ((size_t)bb * TLEN + t) * NCLS + k)
                : (xw + ((size_t)bb * TLEN + t) * WDIM + (k - NCLS));
            float4 v = *(const float4*)src;
            As[kq*4+0][bb] = v.x;
            As[kq*4+1][bb] = v.y;
            As[kq*4+2][bb] = v.z;
            As[kq*4+3][bb] = v.w;
        }
        for (int i = tid; i < 512; i += 256) {
            int kk = i >> 5;
            int nq = i & 31;
            *(float4*)&Bs[kk][nq*4] =
                *(const float4*)(W + (size_t)(k0+kk)*JDIM + n0 + nq*4);
        }
        __syncthreads();
#pragma unroll
        for (int k = 0; k < 16; ++k) {
            float a[8], b8[8];
#pragma unroll
            for (int i = 0; i < 8; ++i) a[i] = As[k][tr*8 + i];
#pragma unroll
            for (int q = 0; q < 4; ++q) { b8[q] = Bs[k][tc*4 + q]; b8[4+q] = Bs[k][tc*4 + 64 + q]; }
#pragma unroll
            for (int i = 0; i < 8; ++i)
#pragma unroll
                for (int j = 0; j < 8; ++j) acc[i][j] = fmaf(a[i], b8[j], acc[i][j]);
        }
        __syncthreads();
    }
    float bv[8];
#pragma unroll
    for (int q = 0; q < 4; ++q) { bv[q] = bias[n0 + tc*4 + q]; bv[4+q] = bias[n0 + tc*4 + 64 + q]; }
#pragma unroll
    for (int i = 0; i < 8; ++i) {
        int b = tr*8 + i;
        size_t row = ((size_t)t * BSZ + b) * JDIM + n0;
        float4 v0 = make_float4(acc[i][0]+bv[0], acc[i][1]+bv[1], acc[i][2]+bv[2], acc[i][3]+bv[3]);
        float4 v1 = make_float4(acc[i][4]+bv[4], acc[i][5]+bv[5], acc[i][6]+bv[6], acc[i][7]+bv[7]);
        *(float4*)(g_Xproj + row + tc*4)      = v0;
        *(float4*)(g_Xproj + row + tc*4 + 64) = v1;
    }
}

// ---------------- smem layout for step kernel (floats) -------------------------------
#define SOF_B    0          // [4][64][128] U chunks (quad buffer)     32768
#define SOF_A    32768      // [16][512]    full h tile                 8192
#define SOF_Z    40960      // [16][128]    z tile                      2048
#define SOF_WSL  43008      // [32][128]    Ws slice                    4096
#define SOF_HN   47104      // [16][32]     h_new tile                   512
#define SOF_IDX  47616      // [16] ints    per-batch argmax              16
#define STEP_SMEM_FLOATS 47632
#define STEP_SMEM_BYTES  (STEP_SMEM_FLOATS * 4)

// ---------------- one LSTM time step: argmax(t-1) prologue + h@U + partial logits ----
// 128 blocks = 8 b-tiles x 16 u-tiles; 256 threads.
// GEMM thread mapping = 4 batches x 2 j-cols: each float2 U read from smem feeds
// 4 batches -> U crossbar traffic halves vs the 2x2 mapping (1 MB/step/SM), putting
// the kernel at the scalar-FFMA issue floor. h reads are warp-uniform broadcasts.
// U quad-buffered via cp.async (prefetch distance 2), one __syncthreads per chunk.
// All arithmetic and ordering identical to passing rounds.
__global__ __launch_bounds__(256) void step_kernel(
    int t, const float* __restrict__ W, const float* __restrict__ Umat,
    const float* __restrict__ Ws, const float* __restrict__ bsv,
    float* __restrict__ out)
{
    extern __shared__ float sm[];
    float* B_s  = sm + SOF_B;
    float* A_s  = sm + SOF_A;
    float* zbuf = sm + SOF_Z;
    float* Wsl  = sm + SOF_WSL;
    float* hn   = sm + SOF_HN;
    int*   idx_s = (int*)(sm + SOF_IDX);

    const int tid = threadIdx.x;
    const int blk = blockIdx.x;
    const int b0  = (blk >> 4) * 16;
    const int ut  = blk & 15;
    const int u0  = ut * 32;
    const float* hin  = g_h[t & 1];
    float*       hout = g_h[(t + 1) & 1];
    const uint32_t sb = smem_u32(sm);

    // ---- group 0: Ws slice + FULL h tile + U chunk 0 ----
    for (int it = 0; it < 4; ++it) {                 // Wsl: 1024 float4
        int idx = tid + it * 256;
        int uu  = idx >> 5;
        int mq  = (idx & 31) * 4;
        cp_async16(sb + (uint32_t)((SOF_WSL + uu * 128 + mq) * 4),
                   Ws + (size_t)(u0 + uu) * NCLS + mq);
    }
    for (int it = 0; it < 8; ++it) {                 // A: 2048 float4 (16 x 512)
        int idx = tid + it * 256;
        int bl  = idx >> 7;
        int kq  = (idx & 127) * 4;
        cp_async16(sb + (uint32_t)((SOF_A + bl * 512 + kq) * 4),
                   hin + (size_t)(b0 + bl) * UNITS + kq);
    }
    for (int it = 0; it < 8; ++it) {                 // B0: 2048 float4
        int idx = tid + it * 256;
        int kk  = idx >> 5;
        int c   = (idx & 31) * 4;
        int g   = c >> 5;
        int uu  = c & 31;
        cp_async16(sb + (uint32_t)((SOF_B + kk * 128 + c) * 4),
                   Umat + (size_t)kk * JDIM + g * 512 + u0 + uu);
    }
    cp_commit();
    // ---- group 1: U chunk 1 ----
    for (int it = 0; it < 8; ++it) {
        int idx = tid + it * 256;
        int kk  = idx >> 5;
        int c   = (idx & 31) * 4;
        int g   = c >> 5;
        int uu  = c & 31;
        cp_async16(sb + (uint32_t)((SOF_B + 8192 + kk * 128 + c) * 4),
                   Umat + (size_t)(64 + kk) * JDIM + g * 512 + u0 + uu);
    }
    cp_commit();

    // ---- prologue: argmax of step t-1 logits for this block's 16 batches ----
    // Identical summation order (ascending ut, then +bias) and first-index
    // tie-breaking as all passing rounds. Warp w handles batches w*2, w*2+1.
    const int lane = tid & 31;
    const int w    = tid >> 5;
    if (t > 0) {
        int m4 = lane * 4;
        float4 bs4 = *(const float4*)(bsv + m4);
#pragma unroll
        for (int pb = 0; pb < 2; ++pb) {
            int bl = w * 2 + pb;
            int b  = b0 + bl;
            const float* pbp = g_part + (size_t)b * (16 * NCLS) + m4;
            float4 s = make_float4(0.0f, 0.0f, 0.0f, 0.0f);
#pragma unroll
            for (int utl = 0; utl < 16; ++utl) {
                float4 v = *(const float4*)(pbp + utl * NCLS);
                s.x += v.x; s.y += v.y; s.z += v.z; s.w += v.w;
            }
            s.x += bs4.x; s.y += bs4.y; s.z += bs4.z; s.w += bs4.w;
            float bv = s.x; int bi = m4;
            if (s.y > bv) { bv = s.y; bi = m4 + 1; }
            if (s.z > bv) { bv = s.z; bi = m4 + 2; }
            if (s.w > bv) { bv = s.w; bi = m4 + 3; }
#pragma unroll
            for (int off = 16; off > 0; off >>= 1) {
                float ov = __shfl_down_sync(0xffffffffu, bv, off);
                int   oi = __shfl_down_sync(0xffffffffu, bi, off);
                if (ov > bv || (ov == bv && oi < bi)) { bv = ov; bi = oi; }
            }
            if (lane == 0) {
                idx_s[bl] = bi;
                if (ut == 0) out[(size_t)b * TLEN + (t - 1)] = (float)bi;
            }
        }
    }

    // ---- GEMM: thread = 4 batches (bq..bq+3) x 2 j-cols (jp, jp+1), scalar fmaf ----
    const int bq = (tid >> 6) * 4;    // 0,4,8,12 (warp-uniform)
    const int jp = (tid & 63) * 2;    // 0..126

    float a0[4], a1[4];
#pragma unroll
    for (int r = 0; r < 4; ++r) { a0[r] = 0.0f; a1[r] = 0.0f; }

#pragma unroll
    for (int kc = 0; kc < 8; ++kc) {
        if (kc < 6) {   // prefetch chunk kc+2 into buf (kc+2)%4
            int nc  = kc + 2;
            int buf = nc & 3;
            for (int it = 0; it < 8; ++it) {
                int idx = tid + it * 256;
                int kk  = idx >> 5;
                int c   = (idx & 31) * 4;
                int g   = c >> 5;
                int uu  = c & 31;
                cp_async16(sb + (uint32_t)((SOF_B + buf * 8192 + kk * 128 + c) * 4),
                           Umat + (size_t)(nc * 64 + kk) * JDIM + g * 512 + u0 + uu);
            }
            cp_commit();
            cp_wait2();
        } else if (kc == 6) {
            cp_wait1();
        } else {
            cp_wait0();
        }
        __syncthreads();
        const float* Bb = B_s + (kc & 3) * 8192;
        const float* Ab = A_s + kc * 64;           // + (bq+r)*512 per row
#pragma unroll 16
        for (int kk = 0; kk < 64; ++kk) {
            float2 u2 = *(const float2*)&Bb[kk * 128 + jp];
#pragma unroll
            for (int r = 0; r < 4; ++r) {
                float hv = Ab[(bq + r) * 512 + kk];   // warp-uniform broadcast
                a0[r] = fmaf(hv, u2.x, a0[r]);
                a1[r] = fmaf(hv, u2.y, a1[r]);
            }
        }
    }
    __syncthreads();
#pragma unroll
    for (int r = 0; r < 4; ++r)
        *(float2*)&zbuf[(bq + r) * 128 + jp] = make_float2(a0[r], a1[r]);
    __syncthreads();

    // ---- finalize: gates + cell update; 2 (b,uu) pairs per thread ----
    const float* xbase = g_Xproj + (size_t)t * BSZ * JDIM;
#pragma unroll
    for (int q = 0; q < 2; ++q) {
        int p  = tid + q * 256;
        int bl = p >> 5;
        int uu = p & 31;
        int b  = b0 + bl;
        int widx = (t == 0) ? -1 : idx_s[bl];
        float z[4];
#pragma unroll
        for (int g = 0; g < 4; ++g) {
            int j = g * 512 + u0 + uu;
            float wrow = (widx < 0) ? g_wsum[j]
                                    : W[(size_t)(KX + widx) * JDIM + j];
            z[g] = zbuf[bl * 128 + g * 32 + uu] + xbase[(size_t)b * JDIM + j] + wrow;
        }
        float ig = my_sigmoid(z[0]);
        float fg = my_sigmoid(z[1]);
        float gg = my_tanh(z[2]);
        float og = my_sigmoid(z[3]);
        size_t ci = (size_t)b * UNITS + u0 + uu;
        float cn = fmaf(fg, g_c[ci], ig * gg);
        g_c[ci] = cn;
        float hv = og * my_tanh(cn);
        hout[ci] = hv;
        hn[bl * 32 + uu] = hv;
    }
    __syncthreads();

    // ---- partial logits for this u-slice: g_part[b][ut][m] ----
    {
        int m  = tid & 127;
        int bh = tid >> 7;            // 0 or 1 -> batches bh*8 .. bh*8+7
        float pacc[8];
#pragma unroll
        for (int r = 0; r < 8; ++r) pacc[r] = 0.0f;
#pragma unroll 8
        for (int uu = 0; uu < 32; ++uu) {
            float wv = Wsl[uu * 128 + m];
#pragma unroll
            for (int r = 0; r < 8; ++r)
                pacc[r] = fmaf(hn[(bh * 8 + r) * 32 + uu], wv, pacc[r]);
        }
#pragma unroll
        for (int r = 0; r < 8; ++r) {
            int b = b0 + bh * 8 + r;
            g_part[(size_t)b * (16 * NCLS) + ut * NCLS + m] = pacc[r];
        }
    }
}

// ---------------- trailing argmax for t = 255 ----------------------------------------
__global__ __launch_bounds__(128) void argmax_last_kernel(
    const float* __restrict__ bsv, float* __restrict__ out)
{
    __shared__ float lg[NCLS];
    const int b   = blockIdx.x;
    const int tid = threadIdx.x;    // = class m

    float s = 0.0f;
    const float* pb = g_part + (size_t)b * (16 * NCLS);
#pragma unroll
    for (int utl = 0; utl < 16; ++utl)
        s += pb[utl * NCLS + tid];
    lg[tid] = s + bsv[tid];
    __syncthreads();

    if (tid < 32) {
        float bv = -INFINITY; int bi = 0x7fffffff;
        for (int mm = tid; mm < 128; mm += 32) {
            float v = lg[mm];
            if (v > bv) { bv = v; bi = mm; }
        }
#pragma unroll
        for (int off = 16; off > 0; off >>= 1) {
            float ov = __shfl_down_sync(0xffffffffu, bv, off);
            int   oi = __shfl_down_sync(0xffffffffu, bi, off);
            if (ov > bv || (ov == bv && oi < bi)) { bv = ov; bi = oi; }
        }
        if (tid == 0)
            out[(size_t)b * TLEN + (TLEN - 1)] = (float)bi;
    }
}

// ---------------- harness entry ------------------------------------------------------
extern "C" void kernel_launch(void* const* d_in, const int* in_sizes, int n_in,
                              void* d_out, int out_size) {
    (void)out_size;
    const float *xc = 0, *xw = 0, *W = 0, *U = 0, *bb = 0, *Ws = 0, *bs = 0;
    for (int i = 0; i < n_in; ++i) {
        switch (in_sizes[i]) {
            case BSZ*TLEN*NCLS:   xc = (const float*)d_in[i]; break;
            case BSZ*TLEN*WDIM:   xw = (const float*)d_in[i]; break;
            case (KX+NCLS)*JDIM:  W  = (const float*)d_in[i]; break;
            case UNITS*JDIM:      U  = (const float*)d_in[i]; break;
            case JDIM:            bb = (const float*)d_in[i]; break;
            case UNITS*NCLS:      Ws = (const float*)d_in[i]; break;
            case NCLS:            bs = (const float*)d_in[i]; break;
            default: break;
        }
    }
    if (!xc || !xw || !W || !U || !bb || !Ws || !bs) {
        xc = (const float*)d_in[0]; xw = (const float*)d_in[1];
        W  = (const float*)d_in[2]; U  = (const float*)d_in[3];
        bb = (const float*)d_in[4]; Ws = (const float*)d_in[5];
        bs = (const float*)d_in[6];
    }
    float* out = (float*)d_out;                // [128,256] as float32

    cudaFuncSetAttribute(step_kernel,
                         cudaFuncAttributeMaxDynamicSharedMemorySize, STEP_SMEM_BYTES);

    init_kernel<<<(BSZ*UNITS + 255) / 256, 256>>>();
    wsum_kernel<<<(JDIM + 255) / 256, 256>>>(W);
    dim3 gx(JDIM / 128, TLEN);
    xproj_kernel<<<gx, 256>>>(xc, xw, W, bb);
    for (int t = 0; t < TLEN; ++t) {
        step_kernel<<<128, 256, STEP_SMEM_BYTES>>>(t, W, U, Ws, bs, out);
    }
    argmax_last_kernel<<<128, 128>>>(bs, out);
}